// round 12
// baseline (speedup 1.0000x reference)
#include <cuda_runtime.h>
#include <cuda_bf16.h>
#include <cstdint>
#include <math.h>

#define BATCH 4096
#define OBJ   16
#define OBS   256
#define HID   512

#if defined(__CUDA_ARCH__) && (defined(__CUDA_ARCH_FEAT_SM103_ALL) || \
    (defined(__CUDA_ARCH_SPECIFIC__) && __CUDA_ARCH_SPECIFIC__ == 1030) || \
    (defined(__CUDA_ARCH_FAMILY_SPECIFIC__) && __CUDA_ARCH_FAMILY_SPECIFIC__ == 1030))
#define HAS_TCGEN05 1
#else
#define HAS_TCGEN05 0
#endif

// ---------------------------------------------------------------------------
// Scratch
// ---------------------------------------------------------------------------
__device__ __nv_bfloat16 g_sbar_h[BATCH * OBS], g_sbar_l[BATCH * OBS];
__device__ __nv_bfloat16 g_h1_h[BATCH * HID], g_h1_l[BATCH * HID];
__device__ __nv_bfloat16 g_h2_h[BATCH * HID], g_h2_l[BATCH * HID];
__device__ __nv_bfloat16 g_W1T_h[HID * OBS], g_W1T_l[HID * OBS];
__device__ __nv_bfloat16 g_W2T_h[HID * HID], g_W2T_l[HID * HID];
__device__ __nv_bfloat16 g_W3T_h[OBS * HID], g_W3T_l[OBS * HID];
// LN partial exchange + phase barriers (32 row bands)
__device__ float2 g_part[32][4][128];
__device__ int    g_cnt0[32];   // phase0 (sbar) done per band
__device__ int    g_cnt[32];    // LN partial barrier
__device__ int    g_cnt1[32];   // phase1 (h1) done per band
__device__ int    g_cnt2[32];   // phase2 (h2) done per band

// ---------------------------------------------------------------------------
// helpers
// ---------------------------------------------------------------------------
__device__ __forceinline__ uint32_t smem_u32(const void* p) {
    uint32_t a;
    asm("{ .reg .u64 t; cvta.to.shared.u64 t, %1; cvt.u32.u64 %0, t; }"
        : "=r"(a) : "l"(p));
    return a;
}
__device__ __forceinline__ uint32_t sw128(uint32_t off) {
    return off ^ ((off >> 3) & 0x70);
}
__device__ __forceinline__ void split_bf16(float v, __nv_bfloat16& hi, __nv_bfloat16& lo) {
    hi = __float2bfloat16(v);
    lo = __float2bfloat16(v - __bfloat162float(hi));
}

#define CP_ASYNC16(smem_a, gptr)                                               \
    asm volatile("cp.async.cg.shared.global [%0], [%1], 16;"                   \
                 :: "r"((uint32_t)(smem_a)), "l"(gptr) : "memory")
#define CP_MBAR_ARRIVE(mbar)                                                   \
    asm volatile("cp.async.mbarrier.arrive.noinc.shared.b64 [%0];"             \
                 :: "r"((uint32_t)(mbar)) : "memory")
#define MBARRIER_INIT(mbar, cnt)                                               \
    asm volatile("mbarrier.init.shared.b64 [%0], %1;"                          \
                 :: "r"((uint32_t)(mbar)), "r"((uint32_t)(cnt)) : "memory")
#define MBARRIER_WAIT_PARITY(mbar_a, par_a) do {                               \
    uint32_t _mb = (uint32_t)(mbar_a);                                         \
    uint32_t _pa = (uint32_t)(par_a);                                          \
    uint32_t _done;                                                            \
    asm volatile("{\n\t.reg .pred p;\n\t"                                      \
        "mbarrier.try_wait.parity.acquire.cta.shared::cta.b64 p, [%1], %2;\n\t"\
        "selp.b32 %0, 1, 0, p;\n\t}"                                           \
        : "=r"(_done) : "r"(_mb), "r"(_pa) : "memory");                        \
    if (!_done) {                                                              \
        asm volatile("{\n\t.reg .pred P1;\n\t"                                 \
            "WL_%=:\n\t"                                                       \
            "mbarrier.try_wait.parity.acquire.cta.shared::cta.b64 P1, [%0], %1, 0x989680;\n\t" \
            "@P1 bra.uni WD_%=;\n\t"                                           \
            "bra.uni WL_%=;\n\t"                                               \
            "WD_%=:\n\t}" :: "r"(_mb), "r"(_pa) : "memory");                   \
    }                                                                          \
} while (0)

#if HAS_TCGEN05
__device__ __forceinline__ uint32_t elect_one() {
    uint32_t pred;
    asm volatile("{\n\t.reg .pred p;\n\telect.sync _|p, 0xFFFFFFFF;\n\t"
                 "selp.b32 %0, 1, 0, p;\n\t}" : "=r"(pred));
    return pred;
}
#define TCGEN05_ALLOC(sm_addr, ncols)                                          \
    asm volatile("tcgen05.alloc.cta_group::1.sync.aligned.shared::cta.b32 [%0], %1;" \
                 :: "r"((uint32_t)(sm_addr)), "r"((uint32_t)(ncols)) : "memory")
#define TCGEN05_DEALLOC(tmem, ncols)                                           \
    asm volatile("tcgen05.dealloc.cta_group::1.sync.aligned.b32 %0, %1;"       \
                 :: "r"(tmem), "r"((uint32_t)(ncols)))
#define TCGEN05_RELINQ()                                                       \
    asm volatile("tcgen05.relinquish_alloc_permit.cta_group::1.sync.aligned;")
#define TCGEN05_COMMIT(mbar)                                                   \
    asm volatile("tcgen05.commit.cta_group::1.mbarrier::arrive::one.shared::cluster.b64 [%0];" \
                 :: "r"((uint32_t)(mbar)) : "memory")
#define TCGEN05_WAIT_LD() asm volatile("tcgen05.wait::ld.sync.aligned;" ::: "memory")
#define TCGEN05_FENCE_AFTER() asm volatile("tcgen05.fence::after_thread_sync;" ::: "memory")
#define FENCE_ASYNC_SHARED() asm volatile("fence.proxy.async.shared::cta;" ::: "memory")

#define TCGEN05_LD_X32(r, tmem_addr)                                           \
    asm volatile("tcgen05.ld.sync.aligned.32x32b.x32.b32 "                     \
        "{%0, %1, %2, %3, %4, %5, %6, %7, "                                    \
        " %8, %9, %10, %11, %12, %13, %14, %15, "                              \
        " %16, %17, %18, %19, %20, %21, %22, %23, "                            \
        " %24, %25, %26, %27, %28, %29, %30, %31}, [%32];"                     \
        : "=r"((r)[0]),  "=r"((r)[1]),  "=r"((r)[2]),  "=r"((r)[3]),           \
          "=r"((r)[4]),  "=r"((r)[5]),  "=r"((r)[6]),  "=r"((r)[7]),           \
          "=r"((r)[8]),  "=r"((r)[9]),  "=r"((r)[10]), "=r"((r)[11]),          \
          "=r"((r)[12]), "=r"((r)[13]), "=r"((r)[14]), "=r"((r)[15]),          \
          "=r"((r)[16]), "=r"((r)[17]), "=r"((r)[18]), "=r"((r)[19]),          \
          "=r"((r)[20]), "=r"((r)[21]), "=r"((r)[22]), "=r"((r)[23]),          \
          "=r"((r)[24]), "=r"((r)[25]), "=r"((r)[26]), "=r"((r)[27]),          \
          "=r"((r)[28]), "=r"((r)[29]), "=r"((r)[30]), "=r"((r)[31])           \
        : "r"(tmem_addr))

__device__ __forceinline__ void mma_bf16_ss(uint32_t d, uint64_t a, uint64_t b,
                                            uint32_t idesc, uint32_t en) {
    asm volatile(
        "{\n\t.reg .pred p;\n\tsetp.ne.u32 p, %4, 0;\n\t"
        "tcgen05.mma.cta_group::1.kind::f16 [%0], %1, %2, %3, {%5, %5, %5, %5}, p;\n\t}"
        :: "r"(d), "l"(a), "l"(b), "r"(idesc), "r"(en), "r"(0u) : "memory");
}
__device__ __forceinline__ uint64_t make_desc(uint32_t addr) {
    return ((uint64_t)2 << 61) | ((uint64_t)1 << 46) | ((uint64_t)64 << 32) |
           ((uint64_t)1 << 16) | ((uint64_t)(addr >> 4) & 0x3FFF);
}
static constexpr uint32_t IDESC_128x128 = 0x8200490u;
#endif  // HAS_TCGEN05

// ---------------------------------------------------------------------------
// Prep (small): weight transpose/split + barrier counter reset
// ---------------------------------------------------------------------------
__global__ void prep_kernel(const float* __restrict__ W1,
                            const float* __restrict__ W2,
                            const float* __restrict__ W3) {
    if (blockIdx.x == 768 ) {
        if (threadIdx.x < 32) {
            g_cnt0[threadIdx.x] = 0;
            g_cnt[threadIdx.x]  = 0;
            g_cnt1[threadIdx.x] = 0;
            g_cnt2[threadIdx.x] = 0;
        }
        return;
    }
    int r = blockIdx.x;
    int bz = r >> 8;
    int rem = r & 255;
    int bx = rem & 15, by = rem >> 4;
    const float* W; __nv_bfloat16 *Th, *Tl; int K, N;
    if (bz == 0)      { W = W1; Th = g_W1T_h; Tl = g_W1T_l; K = OBS; N = HID; }
    else if (bz == 1) { W = W2; Th = g_W2T_h; Tl = g_W2T_l; K = HID; N = HID; }
    else              { W = W3; Th = g_W3T_h; Tl = g_W3T_l; K = HID; N = OBS; }
    int k0 = by * 32, n0 = bx * 32;
    if (k0 >= K || n0 >= N) return;
    __shared__ float t[32][33];
    int tx = threadIdx.x & 31, ty = threadIdx.x >> 5;
#pragma unroll
    for (int i = 0; i < 4; ++i)
        t[ty + i * 8][tx] = W[(size_t)(k0 + ty + i * 8) * N + n0 + tx];
    __syncthreads();
#pragma unroll
    for (int i = 0; i < 4; ++i) {
        int n = ty + i * 8;
        float v = t[tx][n];
        __nv_bfloat16 hi, lo; split_bf16(v, hi, lo);
        size_t o = (size_t)(n0 + n) * K + k0 + tx;
        Th[o] = hi; Tl[o] = lo;
    }
}

// ---------------------------------------------------------------------------
// smem layout (megakernel), non-overlapping by phase
// ---------------------------------------------------------------------------
static constexpr int SM_TMEMPTR = 0;
static constexpr int SM_MBAR    = 16;     // 18 x 8B
static constexpr int SM_BIAS    = 192;
static constexpr int SM_AUX     = 704;    // phase1: 512 f32 W1 rows; phase2: 128 f32 ln_g
static constexpr int SM_LNB2    = 1216;   // phase2 only
static constexpr int SM_MU2     = 1728;   // phase2 only
static constexpr int SM_RS2     = 2752;   // phase2 only
static constexpr int SM_JROW    = 3264;   // phase1 only
static constexpr int SM_TILES   = 4096;
static constexpr int TILE_BYTES = 128 * 128;
static constexpr int NSLOT      = 3;
static constexpr int STG_STRIDE = 132;
static constexpr int GEMM_SMEM  = SM_TILES + NSLOT * 4 * TILE_BYTES;  // 200704
static constexpr int NTHR       = 512;

// ---------------------------------------------------------------------------
// Pipelined bf16-split GEMM mainloop (512 threads); stages D(+s_bias) to s_d.
// ---------------------------------------------------------------------------
#if HAS_TCGEN05
__device__ __forceinline__ void gemm_pipeline(
    char* sm, uint32_t smb, int tid, int wid, int lid, uint32_t tmem,
    const __nv_bfloat16* Ah, const __nv_bfloat16* Al,
    const __nv_bfloat16* BTh, const __nv_bfloat16* BTl,
    int m0, int n0, int Ktot, uint32_t mbofs) {
    const uint32_t mb_full  = smb + mbofs;
    const uint32_t mb_empty = smb + mbofs + 24;
    const __nv_bfloat16* srcs[4] = {Ah, Al, BTh, BTl};
    const int row0s[4] = {m0, m0, n0, n0};
    const int NC = Ktot >> 6;

    auto load_stage = [&](int chunk, int slot) {
        const int kt = chunk << 6;
#pragma unroll
        for (int t = 0; t < 4; ++t) {
            uint32_t st = smb + SM_TILES + (uint32_t)(slot * 4 + t) * TILE_BYTES;
            const __nv_bfloat16* g = srcs[t];
            const int r0 = row0s[t];
#pragma unroll
            for (int ii = 0; ii < 2; ++ii) {
                int idx = tid + ii * NTHR;
                int r = idx >> 3, q = idx & 7;
                CP_ASYNC16(st + sw128(r * 128 + q * 16),
                           g + (size_t)(r0 + r) * Ktot + kt + q * 8);
            }
        }
        CP_MBAR_ARRIVE(mb_full + slot * 8);
    };

#pragma unroll
    for (int c = 0; c < NSLOT; ++c) load_stage(c, c);

    const bool consumer = (wid == 0) && elect_one();
    for (int c = 0; c < NC; ++c) {
        const int s = c % NSLOT;
        const int k = c / NSLOT;
        if (consumer) {
            MBARRIER_WAIT_PARITY(mb_full + s * 8, k & 1);
            FENCE_ASYNC_SHARED();
            uint32_t base = smb + SM_TILES + (uint32_t)(s * 4) * TILE_BYTES;
            uint64_t dAh = make_desc(base);
            uint64_t dAl = make_desc(base + TILE_BYTES);
            uint64_t dBh = make_desc(base + 2 * TILE_BYTES);
            uint64_t dBl = make_desc(base + 3 * TILE_BYTES);
#pragma unroll
            for (int ks = 0; ks < 4; ++ks) {
                mma_bf16_ss(tmem, dAh + ks * 2, dBh + ks * 2, IDESC_128x128,
                            (c > 0 || ks > 0) ? 1u : 0u);
                mma_bf16_ss(tmem, dAh + ks * 2, dBl + ks * 2, IDESC_128x128, 1u);
                mma_bf16_ss(tmem, dAl + ks * 2, dBh + ks * 2, IDESC_128x128, 1u);
            }
            TCGEN05_COMMIT(mb_empty + s * 8);
        }
        if (c + NSLOT < NC) {
            MBARRIER_WAIT_PARITY(mb_empty + s * 8, k & 1);
            load_stage(c + NSLOT, s);
        }
    }
    {
        const int cl = NC - 1;
        MBARRIER_WAIT_PARITY(mb_empty + (cl % NSLOT) * 8, (cl / NSLOT) & 1);
    }
    TCGEN05_FENCE_AFTER();

    // stage D (+bias): 16 warps, one 32x32 block each
    float* s_d = (float*)(sm + SM_TILES);
    const float* s_bias = (const float*)(sm + SM_BIAS);
    {
        const int wq = wid & 3;
        const int cb = (wid >> 2) * 32;
        const int row = wq * 32 + lid;
        uint32_t d[32];
        TCGEN05_LD_X32(d, tmem + cb);
        TCGEN05_WAIT_LD();
#pragma unroll
        for (int c = 0; c < 32; ++c)
            s_d[row * STG_STRIDE + cb + c] = __uint_as_float(d[c]) + s_bias[cb + c];
    }
    __syncthreads();
}
#else
__device__ __forceinline__ void gemm_pipeline(
    char* sm, uint32_t smb, int tid, int wid, int lid, uint32_t tmem,
    const __nv_bfloat16* Ah, const __nv_bfloat16* Al,
    const __nv_bfloat16* BTh, const __nv_bfloat16* BTl,
    int m0, int n0, int Ktot, uint32_t mbofs) {
    float* s_d = (float*)(sm + SM_TILES);
    const float* s_bias = (const float*)(sm + SM_BIAS);
    __syncthreads();
    for (int e = tid; e < 128 * 128; e += NTHR) {
        int r = e >> 7, c = e & 127;
        float acc = 0.f;
        for (int k = 0; k < Ktot; ++k) {
            float a = __bfloat162float(Ah[(size_t)(m0 + r) * Ktot + k]) +
                      __bfloat162float(Al[(size_t)(m0 + r) * Ktot + k]);
            float b = __bfloat162float(BTh[(size_t)(n0 + c) * Ktot + k]) +
                      __bfloat162float(BTl[(size_t)(n0 + c) * Ktot + k]);
            acc += a * b;
        }
        s_d[r * STG_STRIDE + c] = acc + s_bias[c];
    }
    __syncthreads();
}
#endif

// band spin barrier
__device__ __forceinline__ void band_arrive_wait(int* cnt, int target, int tid) {
    __syncthreads();
    if (tid == 0) {
        __threadfence();
        atomicAdd(cnt, 1);
        while (atomicAdd(cnt, 0) < target) {}
        __threadfence();
    }
    __syncthreads();
}

// ---------------------------------------------------------------------------
// Megakernel: phase0 (object mean) -> phase1 (h1) -> phase2 (h2, fused LN)
// -> phase3 (broadcast out). grid (4, 32); 1 CTA/SM, all co-resident.
// ---------------------------------------------------------------------------
__global__ __launch_bounds__(NTHR, 1)
void mega_kernel(const float* __restrict__ states,
                 const int* __restrict__ action,
                 const float* __restrict__ W1,
                 const float* __restrict__ b1,
                 const float* __restrict__ b2,
                 const float* __restrict__ b3,
                 const float* __restrict__ ln_g,
                 const float* __restrict__ ln_b,
                 float* __restrict__ out) {
    extern __shared__ char sm[];
    const uint32_t smb = smem_u32(sm);
    const int tid = threadIdx.x;
    const int wid = tid >> 5;
    const int lid = tid & 31;
    const int x  = blockIdx.x;
    const int by = blockIdx.y;
    const int m0 = by * 128;

    float* s_bias = (float*)(sm + SM_BIAS);
    float* s_aux  = (float*)(sm + SM_AUX);
    int*   s_jrow = (int*)(sm + SM_JROW);
    float* s_b2   = (float*)(sm + SM_LNB2);
    float* s_mu   = (float*)(sm + SM_MU2);
    float* s_rs   = (float*)(sm + SM_RS2);
    float* s_d    = (float*)(sm + SM_TILES);

    uint32_t tmem = 0;
#if HAS_TCGEN05
    if (wid == 0) TCGEN05_ALLOC(smb + SM_TMEMPTR, 128);
    if (tid == 0) {
#pragma unroll
        for (int p = 0; p < 3; ++p) {
#pragma unroll
            for (int s = 0; s < NSLOT; ++s) {
                MBARRIER_INIT(smb + SM_MBAR + p * 48 + s * 8, NTHR);
                MBARRIER_INIT(smb + SM_MBAR + p * 48 + 24 + s * 8, 1);
            }
        }
    }
#endif
    // ---------------- phase 0: object mean for this CTA's 32 rows ---------
    {
        const int r0 = m0 + 32 * x;
#pragma unroll
        for (int it = 0; it < 4; ++it) {
            int row = r0 + it * 8 + (tid >> 6);
            int d4 = tid & 63;
            const float4* src = (const float4*)(states + (size_t)row * OBJ * OBS);
            float4 acc = make_float4(0.f, 0.f, 0.f, 0.f);
#pragma unroll
            for (int o = 0; o < OBJ; ++o) {
                float4 v = src[o * (OBS / 4) + d4];
                acc.x += v.x; acc.y += v.y; acc.z += v.z; acc.w += v.w;
            }
            const float inv = 1.0f / OBJ;
            float vals[4] = {acc.x * inv, acc.y * inv, acc.z * inv, acc.w * inv};
            size_t base = (size_t)row * OBS + d4 * 4;
            __nv_bfloat16 h0, l0, h1, l1;
            split_bf16(vals[0], h0, l0); split_bf16(vals[1], h1, l1);
            *(__nv_bfloat162*)(g_sbar_h + base) = __nv_bfloat162(h0, h1);
            *(__nv_bfloat162*)(g_sbar_l + base) = __nv_bfloat162(l0, l1);
            split_bf16(vals[2], h0, l0); split_bf16(vals[3], h1, l1);
            *(__nv_bfloat162*)(g_sbar_h + base + 2) = __nv_bfloat162(h0, h1);
            *(__nv_bfloat162*)(g_sbar_l + base + 2) = __nv_bfloat162(l0, l1);
        }
        band_arrive_wait(&g_cnt0[by], 4, tid);
    }

    // ---------------- phase 1: h1 ----------------
    {
        const int n0 = x * 128;
        if (tid < 128) {
            s_bias[tid] = b1[n0 + tid];
            s_jrow[tid] = (action[m0 + tid] & 3) * 128;
        }
        s_aux[tid] = W1[(size_t)(256 + (tid >> 7)) * HID + n0 + (tid & 127)];
        __syncthreads();
#if HAS_TCGEN05
        asm volatile("ld.shared.b32 %0, [%1];" : "=r"(tmem) : "r"(smb + SM_TMEMPTR));
#endif
        gemm_pipeline(sm, smb, tid, wid, lid, tmem,
                      g_sbar_h, g_sbar_l, g_W1T_h, g_W1T_l, m0, n0, OBS,
                      SM_MBAR + 0 * 48);
#pragma unroll
        for (int it = 0; it < 8; ++it) {
            int idx = it * NTHR + tid;
            int row = idx >> 5, c4 = (idx & 31) * 4;
            int jr = s_jrow[row];
            float4 v = *(float4*)&s_d[row * STG_STRIDE + c4];
            float f0 = fmaxf(v.x + 0.0625f * s_aux[jr + c4 + 0], 0.f);
            float f1 = fmaxf(v.y + 0.0625f * s_aux[jr + c4 + 1], 0.f);
            float f2 = fmaxf(v.z + 0.0625f * s_aux[jr + c4 + 2], 0.f);
            float f3 = fmaxf(v.w + 0.0625f * s_aux[jr + c4 + 3], 0.f);
            __nv_bfloat16 h0, l0, h1, l1, h2, l2, h3, l3;
            split_bf16(f0, h0, l0); split_bf16(f1, h1, l1);
            split_bf16(f2, h2, l2); split_bf16(f3, h3, l3);
            __nv_bfloat162 hp0(h0, h1), hp1(h2, h3), lp0(l0, l1), lp1(l2, l3);
            uint2 hv = make_uint2(*(uint32_t*)&hp0, *(uint32_t*)&hp1);
            uint2 lv = make_uint2(*(uint32_t*)&lp0, *(uint32_t*)&lp1);
            size_t o = (size_t)(m0 + row) * HID + n0 + c4;
            *(uint2*)(g_h1_h + o) = hv;
            *(uint2*)(g_h1_l + o) = lv;
        }
        band_arrive_wait(&g_cnt1[by], 4, tid);
    }

    // ---------------- phase 2: h2 = relu(LN(h1 @ W2 + b2)) ----------------
    {
        const int n0 = x * 128;
        if (tid < 128) {
            s_bias[tid] = b2[n0 + tid];
            s_aux[tid]  = ln_g[n0 + tid];
            s_b2[tid]   = ln_b[n0 + tid];
        }
        __syncthreads();
        gemm_pipeline(sm, smb, tid, wid, lid, tmem,
                      g_h1_h, g_h1_l, g_W2T_h, g_W2T_l, m0, n0, HID,
                      SM_MBAR + 1 * 48);
        // per-row partials: 4 threads/row
        {
            int prow = tid >> 2, ph = tid & 3;
            float s = 0.f, ss = 0.f;
#pragma unroll
            for (int i = 0; i < 8; ++i) {
                float4 v = *(float4*)&s_d[prow * STG_STRIDE + ph * 32 + i * 4];
                s  += v.x + v.y + v.z + v.w;
                ss += v.x * v.x + v.y * v.y + v.z * v.z + v.w * v.w;
            }
            s  += __shfl_xor_sync(0xffffffffu, s, 1);
            ss += __shfl_xor_sync(0xffffffffu, ss, 1);
            s  += __shfl_xor_sync(0xffffffffu, s, 2);
            ss += __shfl_xor_sync(0xffffffffu, ss, 2);
            if (ph == 0) g_part[by][x][prow] = make_float2(s, ss);
        }
        band_arrive_wait(&g_cnt[by], 4, tid);
        if (tid < 128) {
            float ts = 0.f, tss = 0.f;
#pragma unroll
            for (int r = 0; r < 4; ++r) {
                float2 p = __ldcg(&g_part[by][r][tid]);
                ts += p.x; tss += p.y;
            }
            const float invn = 1.0f / HID;
            float mu = ts * invn;
            float var = tss * invn - mu * mu;
            s_mu[tid] = mu;
            s_rs[tid] = rsqrtf(var + 1e-5f);
        }
        __syncthreads();
#pragma unroll
        for (int it = 0; it < 8; ++it) {
            int idx = it * NTHR + tid;
            int row = idx >> 5, c4 = (idx & 31) * 4;
            float mu = s_mu[row], rs = s_rs[row];
            float4 v = *(float4*)&s_d[row * STG_STRIDE + c4];
            float f0 = fmaxf((v.x - mu) * rs * s_aux[c4 + 0] + s_b2[c4 + 0], 0.f);
            float f1 = fmaxf((v.y - mu) * rs * s_aux[c4 + 1] + s_b2[c4 + 1], 0.f);
            float f2 = fmaxf((v.z - mu) * rs * s_aux[c4 + 2] + s_b2[c4 + 2], 0.f);
            float f3 = fmaxf((v.w - mu) * rs * s_aux[c4 + 3] + s_b2[c4 + 3], 0.f);
            __nv_bfloat16 h0, l0, h1, l1, h2, l2, h3, l3;
            split_bf16(f0, h0, l0); split_bf16(f1, h1, l1);
            split_bf16(f2, h2, l2); split_bf16(f3, h3, l3);
            __nv_bfloat162 hp0(h0, h1), hp1(h2, h3), lp0(l0, l1), lp1(l2, l3);
            uint2 hv = make_uint2(*(uint32_t*)&hp0, *(uint32_t*)&hp1);
            uint2 lv = make_uint2(*(uint32_t*)&lp0, *(uint32_t*)&lp1);
            size_t o = (size_t)(m0 + row) * HID + n0 + c4;
            *(uint2*)(g_h2_h + o) = hv;
            *(uint2*)(g_h2_l + o) = lv;
        }
        band_arrive_wait(&g_cnt2[by], 4, tid);
    }

    // ---------------- phase 3: out = broadcast_obj(h2 @ W3 + b3) ----------
    {
        const int n0 = (x & 1) * 128;
        const int z  = x >> 1;
        if (tid < 128) s_bias[tid] = b3[n0 + tid];
        __syncthreads();
        gemm_pipeline(sm, smb, tid, wid, lid, tmem,
                      g_h2_h, g_h2_l, g_W3T_h, g_W3T_l, m0, n0, HID,
                      SM_MBAR + 2 * 48);
#pragma unroll
        for (int it = 0; it < 8; ++it) {
            int idx = it * NTHR + tid;
            int row = idx >> 5, c4 = (idx & 31) * 4;
            float4 v = *(float4*)&s_d[row * STG_STRIDE + c4];
            size_t base = (size_t)(m0 + row) * (OBJ * OBS) +
                          (size_t)(z * 8) * OBS + n0 + c4;
#pragma unroll
            for (int ob = 0; ob < 8; ++ob)
                *(float4*)(out + base + (size_t)ob * OBS) = v;
        }
    }

#if HAS_TCGEN05
    __syncthreads();
    if (wid == 0) {
        TCGEN05_RELINQ();
        TCGEN05_DEALLOC(tmem, 128);
    }
#endif
}

// ---------------------------------------------------------------------------
extern "C" void kernel_launch(void* const* d_in, const int* in_sizes, int n_in,
                              void* d_out, int out_size) {
    const float* states = (const float*)d_in[0];
    const int*   action = (const int*)d_in[1];
    const float* W1     = (const float*)d_in[2];
    const float* b1     = (const float*)d_in[3];
    const float* W2     = (const float*)d_in[4];
    const float* b2     = (const float*)d_in[5];
    const float* W3     = (const float*)d_in[6];
    const float* b3     = (const float*)d_in[7];
    const float* ln_g   = (const float*)d_in[8];
    const float* ln_b   = (const float*)d_in[9];
    float* out = (float*)d_out;

    cudaFuncSetAttribute(mega_kernel,
                         cudaFuncAttributeMaxDynamicSharedMemorySize, GEMM_SMEM);

    // 0) small prep: weight transpose/split + barrier reset
    prep_kernel<<<769, 256>>>(W1, W2, W3);
    // 1) megakernel: mean -> GEMM1 -> GEMM2+LN -> GEMM3, per-band barriers
    mega_kernel<<<dim3(4, 32), NTHR, GEMM_SMEM>>>(
        states, action, W1, b1, b2, b3, ln_g, ln_b, out);
}

// round 13
// speedup vs baseline: 1.0684x; 1.0684x over previous
#include <cuda_runtime.h>
#include <cuda_bf16.h>
#include <cstdint>
#include <math.h>

#define BATCH 4096
#define OBJ   16
#define OBS   256
#define HID   512

#if defined(__CUDA_ARCH__) && (defined(__CUDA_ARCH_FEAT_SM103_ALL) || \
    (defined(__CUDA_ARCH_SPECIFIC__) && __CUDA_ARCH_SPECIFIC__ == 1030) || \
    (defined(__CUDA_ARCH_FAMILY_SPECIFIC__) && __CUDA_ARCH_FAMILY_SPECIFIC__ == 1030))
#define HAS_TCGEN05 1
#else
#define HAS_TCGEN05 0
#endif

// ---------------------------------------------------------------------------
// Scratch
// ---------------------------------------------------------------------------
__device__ __nv_bfloat16 g_sbar_h[BATCH * OBS], g_sbar_l[BATCH * OBS];
__device__ __nv_bfloat16 g_h1_h[BATCH * HID], g_h1_l[BATCH * HID];
__device__ __nv_bfloat16 g_h2_h[BATCH * HID], g_h2_l[BATCH * HID];
__device__ __nv_bfloat16 g_W1T_h[HID * OBS], g_W1T_l[HID * OBS];
__device__ __nv_bfloat16 g_W2T_h[HID * HID], g_W2T_l[HID * HID];
__device__ __nv_bfloat16 g_W3T_h[OBS * HID], g_W3T_l[OBS * HID];
// LN partial exchange + phase barriers (32 row bands)
__device__ float2 g_part[32][4][128];
__device__ int    g_cnt[32];    // LN partial barrier
__device__ int    g_cnt1[32];   // phase1 (h1) done per band
__device__ int    g_cnt2[32];   // phase2 (h2) done per band

// ---------------------------------------------------------------------------
// helpers
// ---------------------------------------------------------------------------
__device__ __forceinline__ uint32_t smem_u32(const void* p) {
    uint32_t a;
    asm("{ .reg .u64 t; cvta.to.shared.u64 t, %1; cvt.u32.u64 %0, t; }"
        : "=r"(a) : "l"(p));
    return a;
}
__device__ __forceinline__ uint32_t sw128(uint32_t off) {
    return off ^ ((off >> 3) & 0x70);
}
__device__ __forceinline__ void split_bf16(float v, __nv_bfloat16& hi, __nv_bfloat16& lo) {
    hi = __float2bfloat16(v);
    lo = __float2bfloat16(v - __bfloat162float(hi));
}

#define CP_ASYNC16(smem_a, gptr)                                               \
    asm volatile("cp.async.cg.shared.global [%0], [%1], 16;"                   \
                 :: "r"((uint32_t)(smem_a)), "l"(gptr) : "memory")
#define CP_MBAR_ARRIVE(mbar)                                                   \
    asm volatile("cp.async.mbarrier.arrive.noinc.shared.b64 [%0];"             \
                 :: "r"((uint32_t)(mbar)) : "memory")
#define MBARRIER_INIT(mbar, cnt)                                               \
    asm volatile("mbarrier.init.shared.b64 [%0], %1;"                          \
                 :: "r"((uint32_t)(mbar)), "r"((uint32_t)(cnt)) : "memory")
#define MBARRIER_WAIT_PARITY(mbar_a, par_a) do {                               \
    uint32_t _mb = (uint32_t)(mbar_a);                                         \
    uint32_t _pa = (uint32_t)(par_a);                                          \
    uint32_t _done;                                                            \
    asm volatile("{\n\t.reg .pred p;\n\t"                                      \
        "mbarrier.try_wait.parity.acquire.cta.shared::cta.b64 p, [%1], %2;\n\t"\
        "selp.b32 %0, 1, 0, p;\n\t}"                                           \
        : "=r"(_done) : "r"(_mb), "r"(_pa) : "memory");                        \
    if (!_done) {                                                              \
        asm volatile("{\n\t.reg .pred P1;\n\t"                                 \
            "WL_%=:\n\t"                                                       \
            "mbarrier.try_wait.parity.acquire.cta.shared::cta.b64 P1, [%0], %1, 0x989680;\n\t" \
            "@P1 bra.uni WD_%=;\n\t"                                           \
            "bra.uni WL_%=;\n\t"                                               \
            "WD_%=:\n\t}" :: "r"(_mb), "r"(_pa) : "memory");                   \
    }                                                                          \
} while (0)

#if HAS_TCGEN05
__device__ __forceinline__ uint32_t elect_one() {
    uint32_t pred;
    asm volatile("{\n\t.reg .pred p;\n\telect.sync _|p, 0xFFFFFFFF;\n\t"
                 "selp.b32 %0, 1, 0, p;\n\t}" : "=r"(pred));
    return pred;
}
#define TCGEN05_ALLOC(sm_addr, ncols)                                          \
    asm volatile("tcgen05.alloc.cta_group::1.sync.aligned.shared::cta.b32 [%0], %1;" \
                 :: "r"((uint32_t)(sm_addr)), "r"((uint32_t)(ncols)) : "memory")
#define TCGEN05_DEALLOC(tmem, ncols)                                           \
    asm volatile("tcgen05.dealloc.cta_group::1.sync.aligned.b32 %0, %1;"       \
                 :: "r"(tmem), "r"((uint32_t)(ncols)))
#define TCGEN05_RELINQ()                                                       \
    asm volatile("tcgen05.relinquish_alloc_permit.cta_group::1.sync.aligned;")
#define TCGEN05_COMMIT(mbar)                                                   \
    asm volatile("tcgen05.commit.cta_group::1.mbarrier::arrive::one.shared::cluster.b64 [%0];" \
                 :: "r"((uint32_t)(mbar)) : "memory")
#define TCGEN05_WAIT_LD() asm volatile("tcgen05.wait::ld.sync.aligned;" ::: "memory")
#define TCGEN05_FENCE_AFTER() asm volatile("tcgen05.fence::after_thread_sync;" ::: "memory")
#define FENCE_ASYNC_SHARED() asm volatile("fence.proxy.async.shared::cta;" ::: "memory")

#define TCGEN05_LD_X32(r, tmem_addr)                                           \
    asm volatile("tcgen05.ld.sync.aligned.32x32b.x32.b32 "                     \
        "{%0, %1, %2, %3, %4, %5, %6, %7, "                                    \
        " %8, %9, %10, %11, %12, %13, %14, %15, "                              \
        " %16, %17, %18, %19, %20, %21, %22, %23, "                            \
        " %24, %25, %26, %27, %28, %29, %30, %31}, [%32];"                     \
        : "=r"((r)[0]),  "=r"((r)[1]),  "=r"((r)[2]),  "=r"((r)[3]),           \
          "=r"((r)[4]),  "=r"((r)[5]),  "=r"((r)[6]),  "=r"((r)[7]),           \
          "=r"((r)[8]),  "=r"((r)[9]),  "=r"((r)[10]), "=r"((r)[11]),          \
          "=r"((r)[12]), "=r"((r)[13]), "=r"((r)[14]), "=r"((r)[15]),          \
          "=r"((r)[16]), "=r"((r)[17]), "=r"((r)[18]), "=r"((r)[19]),          \
          "=r"((r)[20]), "=r"((r)[21]), "=r"((r)[22]), "=r"((r)[23]),          \
          "=r"((r)[24]), "=r"((r)[25]), "=r"((r)[26]), "=r"((r)[27]),          \
          "=r"((r)[28]), "=r"((r)[29]), "=r"((r)[30]), "=r"((r)[31])           \
        : "r"(tmem_addr))

__device__ __forceinline__ void mma_bf16_ss(uint32_t d, uint64_t a, uint64_t b,
                                            uint32_t idesc, uint32_t en) {
    asm volatile(
        "{\n\t.reg .pred p;\n\tsetp.ne.u32 p, %4, 0;\n\t"
        "tcgen05.mma.cta_group::1.kind::f16 [%0], %1, %2, %3, {%5, %5, %5, %5}, p;\n\t}"
        :: "r"(d), "l"(a), "l"(b), "r"(idesc), "r"(en), "r"(0u) : "memory");
}
__device__ __forceinline__ uint64_t make_desc(uint32_t addr) {
    return ((uint64_t)2 << 61) | ((uint64_t)1 << 46) | ((uint64_t)64 << 32) |
           ((uint64_t)1 << 16) | ((uint64_t)(addr >> 4) & 0x3FFF);
}
static constexpr uint32_t IDESC_128x128 = 0x8200490u;
#endif  // HAS_TCGEN05

// ---------------------------------------------------------------------------
// Prep: object mean + weight transpose/split + barrier counter reset
// ---------------------------------------------------------------------------
__global__ void prep_kernel(const float* __restrict__ states,
                            const float* __restrict__ W1,
                            const float* __restrict__ W2,
                            const float* __restrict__ W3) {
    if (blockIdx.x == 0 && threadIdx.x < 32) {
        g_cnt[threadIdx.x]  = 0;
        g_cnt1[threadIdx.x] = 0;
        g_cnt2[threadIdx.x] = 0;
    }
    if (blockIdx.x < 1024) {
        int lb = threadIdx.x >> 6;
        int d4 = threadIdx.x & 63;
        int b  = blockIdx.x * 4 + lb;
        const float4* src = (const float4*)(states + (size_t)b * OBJ * OBS);
        float4 acc = make_float4(0.f, 0.f, 0.f, 0.f);
#pragma unroll
        for (int o = 0; o < OBJ; ++o) {
            float4 v = src[o * (OBS / 4) + d4];
            acc.x += v.x; acc.y += v.y; acc.z += v.z; acc.w += v.w;
        }
        const float inv = 1.0f / OBJ;
        float vals[4] = {acc.x * inv, acc.y * inv, acc.z * inv, acc.w * inv};
        size_t base = (size_t)b * OBS + d4 * 4;
#pragma unroll
        for (int c = 0; c < 4; ++c) {
            __nv_bfloat16 hi, lo; split_bf16(vals[c], hi, lo);
            g_sbar_h[base + c] = hi; g_sbar_l[base + c] = lo;
        }
    } else {
        int r = blockIdx.x - 1024;
        int bz = r >> 8;
        int rem = r & 255;
        int bx = rem & 15, by = rem >> 4;
        const float* W; __nv_bfloat16 *Th, *Tl; int K, N;
        if (bz == 0)      { W = W1; Th = g_W1T_h; Tl = g_W1T_l; K = OBS; N = HID; }
        else if (bz == 1) { W = W2; Th = g_W2T_h; Tl = g_W2T_l; K = HID; N = HID; }
        else              { W = W3; Th = g_W3T_h; Tl = g_W3T_l; K = HID; N = OBS; }
        int k0 = by * 32, n0 = bx * 32;
        if (k0 >= K || n0 >= N) return;
        __shared__ float t[32][33];
        int tx = threadIdx.x & 31, ty = threadIdx.x >> 5;
#pragma unroll
        for (int i = 0; i < 4; ++i)
            t[ty + i * 8][tx] = W[(size_t)(k0 + ty + i * 8) * N + n0 + tx];
        __syncthreads();
#pragma unroll
        for (int i = 0; i < 4; ++i) {
            int n = ty + i * 8;
            float v = t[tx][n];
            __nv_bfloat16 hi, lo; split_bf16(v, hi, lo);
            size_t o = (size_t)(n0 + n) * K + k0 + tx;
            Th[o] = hi; Tl[o] = lo;
        }
    }
}

// ---------------------------------------------------------------------------
// smem layout (megakernel), non-overlapping by phase
// ---------------------------------------------------------------------------
static constexpr int SM_TMEMPTR = 0;
static constexpr int SM_MBAR    = 16;     // 18 x 8B
static constexpr int SM_BIAS    = 192;
static constexpr int SM_AUX     = 704;    // phase1: 512 f32 W1 rows; phase2: 128 f32 ln_g
static constexpr int SM_LNB2    = 1216;   // phase2 only
static constexpr int SM_MU2     = 1728;   // phase2 only
static constexpr int SM_RS2     = 2752;   // phase2 only
static constexpr int SM_JROW    = 3264;   // phase1 only
static constexpr int SM_TILES   = 4096;
static constexpr int TILE_BYTES = 128 * 128;
static constexpr int NSLOT      = 3;
static constexpr int STG_STRIDE = 132;
static constexpr int GEMM_SMEM  = SM_TILES + NSLOT * 4 * TILE_BYTES;  // 200704
static constexpr int NTHR       = 512;

// band barrier split: arrive (after stores) / wait (before consuming)
__device__ __forceinline__ void band_arrive(int* cnt, int tid) {
    __syncthreads();
    if (tid == 0) {
        __threadfence();
        atomicAdd(cnt, 1);
    }
}
__device__ __forceinline__ void band_wait(int* cnt, int target, int tid) {
    if (tid == 0) {
        while (atomicAdd(cnt, 0) < target) {}
        __threadfence();
    }
    __syncthreads();
}
__device__ __forceinline__ void band_arrive_wait(int* cnt, int target, int tid) {
    band_arrive(cnt, tid);
    band_wait(cnt, target, tid);
}

// ---------------------------------------------------------------------------
// Pipelined bf16-split GEMM (512 threads) with gated prologue:
// B (weight) tiles of the first 3 slots are prefetched BEFORE waiting on the
// band gate; A tiles are loaded after. Stages D(+s_bias) into s_d at the end.
// ---------------------------------------------------------------------------
#if HAS_TCGEN05
__device__ __forceinline__ void gemm_pipeline(
    char* sm, uint32_t smb, int tid, int wid, int lid, uint32_t tmem,
    const __nv_bfloat16* Ah, const __nv_bfloat16* Al,
    const __nv_bfloat16* BTh, const __nv_bfloat16* BTl,
    int m0, int n0, int Ktot, uint32_t mbofs,
    int* gate, int gtar) {
    const uint32_t mb_full  = smb + mbofs;
    const uint32_t mb_empty = smb + mbofs + 24;
    const __nv_bfloat16* srcs[4] = {Ah, Al, BTh, BTl};
    const int row0s[4] = {m0, m0, n0, n0};
    const int NC = Ktot >> 6;

    // load tiles [t0, t1) of one slot
    auto load_tiles = [&](int chunk, int slot, int t0, int t1) {
        const int kt = chunk << 6;
        for (int t = t0; t < t1; ++t) {
            uint32_t st = smb + SM_TILES + (uint32_t)(slot * 4 + t) * TILE_BYTES;
            const __nv_bfloat16* g = srcs[t];
            const int r0 = row0s[t];
#pragma unroll
            for (int ii = 0; ii < 2; ++ii) {
                int idx = tid + ii * NTHR;
                int r = idx >> 3, q = idx & 7;
                CP_ASYNC16(st + sw128(r * 128 + q * 16),
                           g + (size_t)(r0 + r) * Ktot + kt + q * 8);
            }
        }
    };

    // prologue: B tiles first (no dependency), then gate, then A tiles
#pragma unroll
    for (int c = 0; c < NSLOT; ++c) load_tiles(c, c, 2, 4);
    if (gate) band_wait(gate, gtar, tid);
#pragma unroll
    for (int c = 0; c < NSLOT; ++c) {
        load_tiles(c, c, 0, 2);
        CP_MBAR_ARRIVE(mb_full + c * 8);   // covers B too (program order)
    }

    const bool consumer = (wid == 0) && elect_one();
    for (int c = 0; c < NC; ++c) {
        const int s = c % NSLOT;
        const int k = c / NSLOT;
        if (consumer) {
            MBARRIER_WAIT_PARITY(mb_full + s * 8, k & 1);
            FENCE_ASYNC_SHARED();
            uint32_t base = smb + SM_TILES + (uint32_t)(s * 4) * TILE_BYTES;
            uint64_t dAh = make_desc(base);
            uint64_t dAl = make_desc(base + TILE_BYTES);
            uint64_t dBh = make_desc(base + 2 * TILE_BYTES);
            uint64_t dBl = make_desc(base + 3 * TILE_BYTES);
#pragma unroll
            for (int ks = 0; ks < 4; ++ks) {
                mma_bf16_ss(tmem, dAh + ks * 2, dBh + ks * 2, IDESC_128x128,
                            (c > 0 || ks > 0) ? 1u : 0u);
                mma_bf16_ss(tmem, dAh + ks * 2, dBl + ks * 2, IDESC_128x128, 1u);
                mma_bf16_ss(tmem, dAl + ks * 2, dBh + ks * 2, IDESC_128x128, 1u);
            }
            TCGEN05_COMMIT(mb_empty + s * 8);
        }
        if (c + NSLOT < NC) {
            MBARRIER_WAIT_PARITY(mb_empty + s * 8, k & 1);
            load_tiles(c + NSLOT, s, 0, 4);
            CP_MBAR_ARRIVE(mb_full + s * 8);
        }
    }
    {
        const int cl = NC - 1;
        MBARRIER_WAIT_PARITY(mb_empty + (cl % NSLOT) * 8, (cl / NSLOT) & 1);
    }
    TCGEN05_FENCE_AFTER();

    // stage D (+bias): 16 warps, one 32x32 block each
    float* s_d = (float*)(sm + SM_TILES);
    const float* s_bias = (const float*)(sm + SM_BIAS);
    {
        const int wq = wid & 3;
        const int cb = (wid >> 2) * 32;
        const int row = wq * 32 + lid;
        uint32_t d[32];
        TCGEN05_LD_X32(d, tmem + cb);
        TCGEN05_WAIT_LD();
#pragma unroll
        for (int c = 0; c < 32; ++c)
            s_d[row * STG_STRIDE + cb + c] = __uint_as_float(d[c]) + s_bias[cb + c];
    }
    __syncthreads();
}
#else
__device__ __forceinline__ void gemm_pipeline(
    char* sm, uint32_t smb, int tid, int wid, int lid, uint32_t tmem,
    const __nv_bfloat16* Ah, const __nv_bfloat16* Al,
    const __nv_bfloat16* BTh, const __nv_bfloat16* BTl,
    int m0, int n0, int Ktot, uint32_t mbofs,
    int* gate, int gtar) {
    if (gate) band_wait(gate, gtar, threadIdx.x);
    float* s_d = (float*)(sm + SM_TILES);
    const float* s_bias = (const float*)(sm + SM_BIAS);
    __syncthreads();
    for (int e = threadIdx.x; e < 128 * 128; e += NTHR) {
        int r = e >> 7, c = e & 127;
        float acc = 0.f;
        for (int k = 0; k < Ktot; ++k) {
            float a = __bfloat162float(Ah[(size_t)(m0 + r) * Ktot + k]) +
                      __bfloat162float(Al[(size_t)(m0 + r) * Ktot + k]);
            float b = __bfloat162float(BTh[(size_t)(n0 + c) * Ktot + k]) +
                      __bfloat162float(BTl[(size_t)(n0 + c) * Ktot + k]);
            acc += a * b;
        }
        s_d[r * STG_STRIDE + c] = acc + s_bias[c];
    }
    __syncthreads();
}
#endif

// ---------------------------------------------------------------------------
// Megakernel: phase1 -> phase2(+LN) -> phase3, band barriers with B-prefetch
// overlap. grid (4, 32); 1 CTA/SM, all co-resident.
// ---------------------------------------------------------------------------
__global__ __launch_bounds__(NTHR, 1)
void mega_kernel(const int* __restrict__ action,
                 const float* __restrict__ W1,
                 const float* __restrict__ b1,
                 const float* __restrict__ b2,
                 const float* __restrict__ b3,
                 const float* __restrict__ ln_g,
                 const float* __restrict__ ln_b,
                 float* __restrict__ out) {
    extern __shared__ char sm[];
    const uint32_t smb = smem_u32(sm);
    const int tid = threadIdx.x;
    const int wid = tid >> 5;
    const int lid = tid & 31;
    const int x  = blockIdx.x;
    const int by = blockIdx.y;
    const int m0 = by * 128;

    float* s_bias = (float*)(sm + SM_BIAS);
    float* s_aux  = (float*)(sm + SM_AUX);
    int*   s_jrow = (int*)(sm + SM_JROW);
    float* s_b2   = (float*)(sm + SM_LNB2);
    float* s_mu   = (float*)(sm + SM_MU2);
    float* s_rs   = (float*)(sm + SM_RS2);
    float* s_d    = (float*)(sm + SM_TILES);

    uint32_t tmem = 0;
#if HAS_TCGEN05
    if (wid == 0) TCGEN05_ALLOC(smb + SM_TMEMPTR, 128);
    if (tid == 0) {
#pragma unroll
        for (int p = 0; p < 3; ++p) {
#pragma unroll
            for (int s = 0; s < NSLOT; ++s) {
                MBARRIER_INIT(smb + SM_MBAR + p * 48 + s * 8, NTHR);
                MBARRIER_INIT(smb + SM_MBAR + p * 48 + 24 + s * 8, 1);
            }
        }
    }
#endif
    // ---------------- phase 1: h1 ----------------
    {
        const int n0 = x * 128;
        if (tid < 128) {
            s_bias[tid] = b1[n0 + tid];
            s_jrow[tid] = (action[m0 + tid] & 3) * 128;
        }
        s_aux[tid] = W1[(size_t)(256 + (tid >> 7)) * HID + n0 + (tid & 127)];
        __syncthreads();
#if HAS_TCGEN05
        asm volatile("ld.shared.b32 %0, [%1];" : "=r"(tmem) : "r"(smb + SM_TMEMPTR));
#endif
        gemm_pipeline(sm, smb, tid, wid, lid, tmem,
                      g_sbar_h, g_sbar_l, g_W1T_h, g_W1T_l, m0, n0, OBS,
                      SM_MBAR + 0 * 48, nullptr, 0);
#pragma unroll
        for (int it = 0; it < 8; ++it) {
            int idx = it * NTHR + tid;
            int row = idx >> 5, c4 = (idx & 31) * 4;
            int jr = s_jrow[row];
            float4 v = *(float4*)&s_d[row * STG_STRIDE + c4];
            float f0 = fmaxf(v.x + 0.0625f * s_aux[jr + c4 + 0], 0.f);
            float f1 = fmaxf(v.y + 0.0625f * s_aux[jr + c4 + 1], 0.f);
            float f2 = fmaxf(v.z + 0.0625f * s_aux[jr + c4 + 2], 0.f);
            float f3 = fmaxf(v.w + 0.0625f * s_aux[jr + c4 + 3], 0.f);
            __nv_bfloat16 h0, l0, h1, l1, h2, l2, h3, l3;
            split_bf16(f0, h0, l0); split_bf16(f1, h1, l1);
            split_bf16(f2, h2, l2); split_bf16(f3, h3, l3);
            __nv_bfloat162 hp0(h0, h1), hp1(h2, h3), lp0(l0, l1), lp1(l2, l3);
            uint2 hv = make_uint2(*(uint32_t*)&hp0, *(uint32_t*)&hp1);
            uint2 lv = make_uint2(*(uint32_t*)&lp0, *(uint32_t*)&lp1);
            size_t o = (size_t)(m0 + row) * HID + n0 + c4;
            *(uint2*)(g_h1_h + o) = hv;
            *(uint2*)(g_h1_l + o) = lv;
        }
        band_arrive(&g_cnt1[by], tid);   // wait happens inside next pipeline
    }

    // ---------------- phase 2: h2 = relu(LN(h1 @ W2 + b2)) ----------------
    {
        const int n0 = x * 128;
        if (tid < 128) {
            s_bias[tid] = b2[n0 + tid];
            s_aux[tid]  = ln_g[n0 + tid];
            s_b2[tid]   = ln_b[n0 + tid];
        }
        __syncthreads();
        gemm_pipeline(sm, smb, tid, wid, lid, tmem,
                      g_h1_h, g_h1_l, g_W2T_h, g_W2T_l, m0, n0, HID,
                      SM_MBAR + 1 * 48, &g_cnt1[by], 4);
        // per-row partials: 4 threads/row
        {
            int prow = tid >> 2, ph = tid & 3;
            float s = 0.f, ss = 0.f;
#pragma unroll
            for (int i = 0; i < 8; ++i) {
                float4 v = *(float4*)&s_d[prow * STG_STRIDE + ph * 32 + i * 4];
                s  += v.x + v.y + v.z + v.w;
                ss += v.x * v.x + v.y * v.y + v.z * v.z + v.w * v.w;
            }
            s  += __shfl_xor_sync(0xffffffffu, s, 1);
            ss += __shfl_xor_sync(0xffffffffu, ss, 1);
            s  += __shfl_xor_sync(0xffffffffu, s, 2);
            ss += __shfl_xor_sync(0xffffffffu, ss, 2);
            if (ph == 0) g_part[by][x][prow] = make_float2(s, ss);
        }
        band_arrive_wait(&g_cnt[by], 4, tid);
        if (tid < 128) {
            float ts = 0.f, tss = 0.f;
#pragma unroll
            for (int r = 0; r < 4; ++r) {
                float2 p = __ldcg(&g_part[by][r][tid]);
                ts += p.x; tss += p.y;
            }
            const float invn = 1.0f / HID;
            float mu = ts * invn;
            float var = tss * invn - mu * mu;
            s_mu[tid] = mu;
            s_rs[tid] = rsqrtf(var + 1e-5f);
        }
        __syncthreads();
#pragma unroll
        for (int it = 0; it < 8; ++it) {
            int idx = it * NTHR + tid;
            int row = idx >> 5, c4 = (idx & 31) * 4;
            float mu = s_mu[row], rs = s_rs[row];
            float4 v = *(float4*)&s_d[row * STG_STRIDE + c4];
            float f0 = fmaxf((v.x - mu) * rs * s_aux[c4 + 0] + s_b2[c4 + 0], 0.f);
            float f1 = fmaxf((v.y - mu) * rs * s_aux[c4 + 1] + s_b2[c4 + 1], 0.f);
            float f2 = fmaxf((v.z - mu) * rs * s_aux[c4 + 2] + s_b2[c4 + 2], 0.f);
            float f3 = fmaxf((v.w - mu) * rs * s_aux[c4 + 3] + s_b2[c4 + 3], 0.f);
            __nv_bfloat16 h0, l0, h1, l1, h2, l2, h3, l3;
            split_bf16(f0, h0, l0); split_bf16(f1, h1, l1);
            split_bf16(f2, h2, l2); split_bf16(f3, h3, l3);
            __nv_bfloat162 hp0(h0, h1), hp1(h2, h3), lp0(l0, l1), lp1(l2, l3);
            uint2 hv = make_uint2(*(uint32_t*)&hp0, *(uint32_t*)&hp1);
            uint2 lv = make_uint2(*(uint32_t*)&lp0, *(uint32_t*)&lp1);
            size_t o = (size_t)(m0 + row) * HID + n0 + c4;
            *(uint2*)(g_h2_h + o) = hv;
            *(uint2*)(g_h2_l + o) = lv;
        }
        band_arrive(&g_cnt2[by], tid);   // wait inside next pipeline
    }

    // ---------------- phase 3: out = broadcast_obj(h2 @ W3 + b3) ----------
    {
        const int n0 = (x & 1) * 128;
        const int z  = x >> 1;
        if (tid < 128) s_bias[tid] = b3[n0 + tid];
        __syncthreads();
        gemm_pipeline(sm, smb, tid, wid, lid, tmem,
                      g_h2_h, g_h2_l, g_W3T_h, g_W3T_l, m0, n0, HID,
                      SM_MBAR + 2 * 48, &g_cnt2[by], 4);
#pragma unroll
        for (int it = 0; it < 8; ++it) {
            int idx = it * NTHR + tid;
            int row = idx >> 5, c4 = (idx & 31) * 4;
            float4 v = *(float4*)&s_d[row * STG_STRIDE + c4];
            size_t base = (size_t)(m0 + row) * (OBJ * OBS) +
                          (size_t)(z * 8) * OBS + n0 + c4;
#pragma unroll
            for (int ob = 0; ob < 8; ++ob)
                *(float4*)(out + base + (size_t)ob * OBS) = v;
        }
    }

#if HAS_TCGEN05
    __syncthreads();
    if (wid == 0) {
        TCGEN05_RELINQ();
        TCGEN05_DEALLOC(tmem, 128);
    }
#endif
}

// ---------------------------------------------------------------------------
extern "C" void kernel_launch(void* const* d_in, const int* in_sizes, int n_in,
                              void* d_out, int out_size) {
    const float* states = (const float*)d_in[0];
    const int*   action = (const int*)d_in[1];
    const float* W1     = (const float*)d_in[2];
    const float* b1     = (const float*)d_in[3];
    const float* W2     = (const float*)d_in[4];
    const float* b2     = (const float*)d_in[5];
    const float* W3     = (const float*)d_in[6];
    const float* b3     = (const float*)d_in[7];
    const float* ln_g   = (const float*)d_in[8];
    const float* ln_b   = (const float*)d_in[9];
    float* out = (float*)d_out;

    cudaFuncSetAttribute(mega_kernel,
                         cudaFuncAttributeMaxDynamicSharedMemorySize, GEMM_SMEM);

    // 0) prep: object mean + weight transpose/split + barrier reset
    prep_kernel<<<1792, 256>>>(states, W1, W2, W3);
    // 1) megakernel: GEMM1 -> GEMM2+LN -> GEMM3, band barriers + B-prefetch
    mega_kernel<<<dim3(4, 32), NTHR, GEMM_SMEM>>>(
        action, W1, b1, b2, b3, ln_g, ln_b, out);
}

// round 15
// speedup vs baseline: 1.0695x; 1.0011x over previous
#include <cuda_runtime.h>
#include <cuda.h>
#include <cuda_bf16.h>
#include <cstdint>
#include <math.h>

#define BATCH 4096
#define OBJ   16
#define OBS   256
#define HID   512

#if defined(__CUDA_ARCH__) && (defined(__CUDA_ARCH_FEAT_SM103_ALL) || \
    (defined(__CUDA_ARCH_SPECIFIC__) && __CUDA_ARCH_SPECIFIC__ == 1030) || \
    (defined(__CUDA_ARCH_FAMILY_SPECIFIC__) && __CUDA_ARCH_FAMILY_SPECIFIC__ == 1030))
#define HAS_TCGEN05 1
#else
#define HAS_TCGEN05 0
#endif

// ---------------------------------------------------------------------------
// Scratch
// ---------------------------------------------------------------------------
__device__ __nv_bfloat16 g_sbar_h[BATCH * OBS], g_sbar_l[BATCH * OBS];
__device__ __nv_bfloat16 g_h1_h[BATCH * HID], g_h1_l[BATCH * HID];
__device__ __nv_bfloat16 g_h2_h[BATCH * HID], g_h2_l[BATCH * HID];
__device__ __nv_bfloat16 g_W1T_h[HID * OBS], g_W1T_l[HID * OBS];
__device__ __nv_bfloat16 g_W2T_h[HID * HID], g_W2T_l[HID * HID];
__device__ __nv_bfloat16 g_W3T_h[OBS * HID], g_W3T_l[OBS * HID];
// TMA descriptors: 0 sbar_h 1 sbar_l 2 W1T_h 3 W1T_l 4 h1_h 5 h1_l
//                  6 W2T_h 7 W2T_l 8 h2_h 9 h2_l 10 W3T_h 11 W3T_l
__device__ __align__(128) CUtensorMap g_tmaps[12];
// LN partial exchange + phase barriers (32 row bands)
__device__ float2 g_part[32][4][128];
__device__ int    g_cnt[32];
__device__ int    g_cnt1[32];
__device__ int    g_cnt2[32];

// ---------------------------------------------------------------------------
// helpers
// ---------------------------------------------------------------------------
__device__ __forceinline__ uint32_t smem_u32(const void* p) {
    uint32_t a;
    asm("{ .reg .u64 t; cvta.to.shared.u64 t, %1; cvt.u32.u64 %0, t; }"
        : "=r"(a) : "l"(p));
    return a;
}
__device__ __forceinline__ uint32_t sw128(uint32_t off) {
    return off ^ ((off >> 3) & 0x70);
}
__device__ __forceinline__ void split_bf16(float v, __nv_bfloat16& hi, __nv_bfloat16& lo) {
    hi = __float2bfloat16(v);
    lo = __float2bfloat16(v - __bfloat162float(hi));
}

#define MBARRIER_INIT(mbar, cnt)                                               \
    asm volatile("mbarrier.init.shared.b64 [%0], %1;"                          \
                 :: "r"((uint32_t)(mbar)), "r"((uint32_t)(cnt)) : "memory")
#define MBARRIER_EXPECT_TX(mbar, bytes)                                        \
    asm volatile("mbarrier.arrive.expect_tx.shared.b64 _, [%0], %1;"           \
                 :: "r"((uint32_t)(mbar)), "r"((uint32_t)(bytes)) : "memory")
#define MBARRIER_WAIT_PARITY(mbar_a, par_a) do {                               \
    uint32_t _mb = (uint32_t)(mbar_a);                                         \
    uint32_t _pa = (uint32_t)(par_a);                                          \
    uint32_t _done;                                                            \
    asm volatile("{\n\t.reg .pred p;\n\t"                                      \
        "mbarrier.try_wait.parity.acquire.cta.shared::cta.b64 p, [%1], %2;\n\t"\
        "selp.b32 %0, 1, 0, p;\n\t}"                                           \
        : "=r"(_done) : "r"(_mb), "r"(_pa) : "memory");                        \
    if (!_done) {                                                              \
        asm volatile("{\n\t.reg .pred P1;\n\t"                                 \
            "WL_%=:\n\t"                                                       \
            "mbarrier.try_wait.parity.acquire.cta.shared::cta.b64 P1, [%0], %1, 0x989680;\n\t" \
            "@P1 bra.uni WD_%=;\n\t"                                           \
            "bra.uni WL_%=;\n\t"                                               \
            "WD_%=:\n\t}" :: "r"(_mb), "r"(_pa) : "memory");                   \
    }                                                                          \
} while (0)
#define FENCE_PROXY_ASYNC() asm volatile("fence.proxy.async;" ::: "memory")

#if HAS_TCGEN05
#define TMA_LOAD_2D(dst, map, cx, cy, mbar)                                    \
    asm volatile("cp.async.bulk.tensor.2d.shared::cta.global.tile.mbarrier::complete_tx::bytes " \
                 "[%0], [%1, {%2, %3}], [%4];"                                 \
                 :: "r"((uint32_t)(dst)), "l"(map), "r"((int)(cx)),            \
                    "r"((int)(cy)), "r"((uint32_t)(mbar)) : "memory")
#define TCGEN05_ALLOC(sm_addr, ncols)                                          \
    asm volatile("tcgen05.alloc.cta_group::1.sync.aligned.shared::cta.b32 [%0], %1;" \
                 :: "r"((uint32_t)(sm_addr)), "r"((uint32_t)(ncols)) : "memory")
#define TCGEN05_DEALLOC(tmem, ncols)                                           \
    asm volatile("tcgen05.dealloc.cta_group::1.sync.aligned.b32 %0, %1;"       \
                 :: "r"(tmem), "r"((uint32_t)(ncols)))
#define TCGEN05_RELINQ()                                                       \
    asm volatile("tcgen05.relinquish_alloc_permit.cta_group::1.sync.aligned;")
#define TCGEN05_COMMIT(mbar)                                                   \
    asm volatile("tcgen05.commit.cta_group::1.mbarrier::arrive::one.shared::cluster.b64 [%0];" \
                 :: "r"((uint32_t)(mbar)) : "memory")
#define TCGEN05_WAIT_LD() asm volatile("tcgen05.wait::ld.sync.aligned;" ::: "memory")
#define TCGEN05_FENCE_AFTER() asm volatile("tcgen05.fence::after_thread_sync;" ::: "memory")
#define FENCE_ASYNC_SHARED() asm volatile("fence.proxy.async.shared::cta;" ::: "memory")

#define TCGEN05_LD_X32(r, tmem_addr)                                           \
    asm volatile("tcgen05.ld.sync.aligned.32x32b.x32.b32 "                     \
        "{%0, %1, %2, %3, %4, %5, %6, %7, "                                    \
        " %8, %9, %10, %11, %12, %13, %14, %15, "                              \
        " %16, %17, %18, %19, %20, %21, %22, %23, "                            \
        " %24, %25, %26, %27, %28, %29, %30, %31}, [%32];"                     \
        : "=r"((r)[0]),  "=r"((r)[1]),  "=r"((r)[2]),  "=r"((r)[3]),           \
          "=r"((r)[4]),  "=r"((r)[5]),  "=r"((r)[6]),  "=r"((r)[7]),           \
          "=r"((r)[8]),  "=r"((r)[9]),  "=r"((r)[10]), "=r"((r)[11]),          \
          "=r"((r)[12]), "=r"((r)[13]), "=r"((r)[14]), "=r"((r)[15]),          \
          "=r"((r)[16]), "=r"((r)[17]), "=r"((r)[18]), "=r"((r)[19]),          \
          "=r"((r)[20]), "=r"((r)[21]), "=r"((r)[22]), "=r"((r)[23]),          \
          "=r"((r)[24]), "=r"((r)[25]), "=r"((r)[26]), "=r"((r)[27]),          \
          "=r"((r)[28]), "=r"((r)[29]), "=r"((r)[30]), "=r"((r)[31])           \
        : "r"(tmem_addr))

__device__ __forceinline__ void mma_bf16_ss(uint32_t d, uint64_t a, uint64_t b,
                                            uint32_t idesc, uint32_t en) {
    asm volatile(
        "{\n\t.reg .pred p;\n\tsetp.ne.u32 p, %4, 0;\n\t"
        "tcgen05.mma.cta_group::1.kind::f16 [%0], %1, %2, %3, {%5, %5, %5, %5}, p;\n\t}"
        :: "r"(d), "l"(a), "l"(b), "r"(idesc), "r"(en), "r"(0u) : "memory");
}
__device__ __forceinline__ uint64_t make_desc(uint32_t addr) {
    return ((uint64_t)2 << 61) | ((uint64_t)1 << 46) | ((uint64_t)64 << 32) |
           ((uint64_t)1 << 16) | ((uint64_t)(addr >> 4) & 0x3FFF);
}
static constexpr uint32_t IDESC_128x128 = 0x8200490u;
#endif  // HAS_TCGEN05

// ---------------------------------------------------------------------------
// Prep: object mean + weight transpose/split + barrier counter reset
// ---------------------------------------------------------------------------
__global__ void prep_kernel(const float* __restrict__ states,
                            const float* __restrict__ W1,
                            const float* __restrict__ W2,
                            const float* __restrict__ W3) {
    if (blockIdx.x == 0 && threadIdx.x < 32) {
        g_cnt[threadIdx.x]  = 0;
        g_cnt1[threadIdx.x] = 0;
        g_cnt2[threadIdx.x] = 0;
    }
    if (blockIdx.x < 1024) {
        int lb = threadIdx.x >> 6;
        int d4 = threadIdx.x & 63;
        int b  = blockIdx.x * 4 + lb;
        const float4* src = (const float4*)(states + (size_t)b * OBJ * OBS);
        float4 acc = make_float4(0.f, 0.f, 0.f, 0.f);
#pragma unroll
        for (int o = 0; o < OBJ; ++o) {
            float4 v = src[o * (OBS / 4) + d4];
            acc.x += v.x; acc.y += v.y; acc.z += v.z; acc.w += v.w;
        }
        const float inv = 1.0f / OBJ;
        float vals[4] = {acc.x * inv, acc.y * inv, acc.z * inv, acc.w * inv};
        size_t base = (size_t)b * OBS + d4 * 4;
#pragma unroll
        for (int c = 0; c < 4; ++c) {
            __nv_bfloat16 hi, lo; split_bf16(vals[c], hi, lo);
            g_sbar_h[base + c] = hi; g_sbar_l[base + c] = lo;
        }
    } else {
        int r = blockIdx.x - 1024;
        int bz = r >> 8;
        int rem = r & 255;
        int bx = rem & 15, by = rem >> 4;
        const float* W; __nv_bfloat16 *Th, *Tl; int K, N;
        if (bz == 0)      { W = W1; Th = g_W1T_h; Tl = g_W1T_l; K = OBS; N = HID; }
        else if (bz == 1) { W = W2; Th = g_W2T_h; Tl = g_W2T_l; K = HID; N = HID; }
        else              { W = W3; Th = g_W3T_h; Tl = g_W3T_l; K = HID; N = OBS; }
        int k0 = by * 32, n0 = bx * 32;
        if (k0 >= K || n0 >= N) return;
        __shared__ float t[32][33];
        int tx = threadIdx.x & 31, ty = threadIdx.x >> 5;
#pragma unroll
        for (int i = 0; i < 4; ++i)
            t[ty + i * 8][tx] = W[(size_t)(k0 + ty + i * 8) * N + n0 + tx];
        __syncthreads();
#pragma unroll
        for (int i = 0; i < 4; ++i) {
            int n = ty + i * 8;
            float v = t[tx][n];
            __nv_bfloat16 hi, lo; split_bf16(v, hi, lo);
            size_t o = (size_t)(n0 + n) * K + k0 + tx;
            Th[o] = hi; Tl[o] = lo;
        }
    }
}

// ---------------------------------------------------------------------------
// smem layout (megakernel)
// ---------------------------------------------------------------------------
static constexpr int SM_TMEMPTR = 0;
static constexpr int SM_MBAR    = 16;     // 18 x 8B
static constexpr int SM_BIAS    = 192;
static constexpr int SM_AUX     = 704;
static constexpr int SM_LNB2    = 1216;
static constexpr int SM_MU2     = 1728;
static constexpr int SM_RS2     = 2752;
static constexpr int SM_JROW    = 3264;
static constexpr int SM_TILES   = 4096;
static constexpr int TILE_BYTES = 128 * 128;
static constexpr int NSLOT      = 3;
static constexpr int STG_STRIDE = 132;
static constexpr int GEMM_SMEM  = SM_TILES + NSLOT * 4 * TILE_BYTES;  // 200704
static constexpr int NTHR       = 512;
static constexpr uint32_t SLOT_BYTES = 4 * TILE_BYTES;  // 64KB

// band barrier helpers (async-proxy fenced release)
__device__ __forceinline__ void band_arrive(int* cnt, int tid) {
    __syncthreads();
    if (tid == 0) {
        __threadfence();
        FENCE_PROXY_ASYNC();      // order generic stores before async-proxy reads
        atomicAdd(cnt, 1);
    }
}
__device__ __forceinline__ void band_arrive_wait(int* cnt, int target, int tid) {
    band_arrive(cnt, tid);
    if (tid == 0) {
        while (atomicAdd(cnt, 0) < target) {}
        __threadfence();
    }
    __syncthreads();
}

// ---------------------------------------------------------------------------
// TMA-fed bf16-split GEMM pipeline. tid0 drives loads + MMA + drain; the CTA
// is released by __syncthreads. Stages D(+s_bias) into s_d (16 warps).
// ---------------------------------------------------------------------------
#if HAS_TCGEN05
__device__ __forceinline__ void gemm_pipeline(
    char* sm, uint32_t smb, int tid, int wid, int lid, uint32_t tmem,
    const CUtensorMap* mAh, const CUtensorMap* mAl,
    const CUtensorMap* mBh, const CUtensorMap* mBl,
    int m0, int n0, int Ktot, uint32_t mbofs,
    int* gate, int gtar) {
    const uint32_t mb_full  = smb + mbofs;
    const uint32_t mb_empty = smb + mbofs + 24;
    const int NC = Ktot >> 6;

    if (tid == 0) {
        FENCE_ASYNC_SHARED();   // prior generic s_d accesses before TMA smem writes
        // prologue: expect + B (weight) tiles — gate-independent
#pragma unroll
        for (int s = 0; s < NSLOT; ++s) {
            uint32_t base = smb + SM_TILES + (uint32_t)s * SLOT_BYTES;
            MBARRIER_EXPECT_TX(mb_full + s * 8, SLOT_BYTES);
            int kt = s << 6;
            TMA_LOAD_2D(base + 2 * TILE_BYTES, mBh, kt, n0, mb_full + s * 8);
            TMA_LOAD_2D(base + 3 * TILE_BYTES, mBl, kt, n0, mb_full + s * 8);
        }
        if (gate) {
            while (atomicAdd(gate, 0) < gtar) {}
            __threadfence();
            FENCE_PROXY_ASYNC();   // producer's generic stores -> our TMA reads
        }
#pragma unroll
        for (int s = 0; s < NSLOT; ++s) {
            uint32_t base = smb + SM_TILES + (uint32_t)s * SLOT_BYTES;
            int kt = s << 6;
            TMA_LOAD_2D(base, mAh, kt, m0, mb_full + s * 8);
            TMA_LOAD_2D(base + TILE_BYTES, mAl, kt, m0, mb_full + s * 8);
        }
        // mainloop
        for (int c = 0; c < NC; ++c) {
            const int s = c % NSLOT;
            const int k = c / NSLOT;
            MBARRIER_WAIT_PARITY(mb_full + s * 8, k & 1);
            uint32_t base = smb + SM_TILES + (uint32_t)s * SLOT_BYTES;
            uint64_t dAh = make_desc(base);
            uint64_t dAl = make_desc(base + TILE_BYTES);
            uint64_t dBh = make_desc(base + 2 * TILE_BYTES);
            uint64_t dBl = make_desc(base + 3 * TILE_BYTES);
#pragma unroll
            for (int ks = 0; ks < 4; ++ks) {
                mma_bf16_ss(tmem, dAh + ks * 2, dBh + ks * 2, IDESC_128x128,
                            (c > 0 || ks > 0) ? 1u : 0u);
                mma_bf16_ss(tmem, dAh + ks * 2, dBl + ks * 2, IDESC_128x128, 1u);
                mma_bf16_ss(tmem, dAl + ks * 2, dBh + ks * 2, IDESC_128x128, 1u);
            }
            TCGEN05_COMMIT(mb_empty + s * 8);
            if (c + NSLOT < NC) {
                MBARRIER_WAIT_PARITY(mb_empty + s * 8, k & 1);
                MBARRIER_EXPECT_TX(mb_full + s * 8, SLOT_BYTES);
                int kt = (c + NSLOT) << 6;
                TMA_LOAD_2D(base, mAh, kt, m0, mb_full + s * 8);
                TMA_LOAD_2D(base + TILE_BYTES, mAl, kt, m0, mb_full + s * 8);
                TMA_LOAD_2D(base + 2 * TILE_BYTES, mBh, kt, n0, mb_full + s * 8);
                TMA_LOAD_2D(base + 3 * TILE_BYTES, mBl, kt, n0, mb_full + s * 8);
            }
        }
        // drain: tid0's program-order parity is the correct one (R14 bug fix:
        // other threads' bare parity wait fires on the FIRST flip, not last)
        const int cl = NC - 1;
        MBARRIER_WAIT_PARITY(mb_empty + (cl % NSLOT) * 8, (cl / NSLOT) & 1);
    }
    __syncthreads();            // release CTA only after tid0 drained all MMAs
    TCGEN05_FENCE_AFTER();

    // stage D (+bias): 16 warps, one 32x32 block each
    float* s_d = (float*)(sm + SM_TILES);
    const float* s_bias = (const float*)(sm + SM_BIAS);
    {
        const int wq = wid & 3;
        const int cb = (wid >> 2) * 32;
        const int row = wq * 32 + lid;
        uint32_t d[32];
        TCGEN05_LD_X32(d, tmem + cb);
        TCGEN05_WAIT_LD();
#pragma unroll
        for (int c = 0; c < 32; ++c)
            s_d[row * STG_STRIDE + cb + c] = __uint_as_float(d[c]) + s_bias[cb + c];
    }
    __syncthreads();
}
#else
__device__ __forceinline__ void gemm_pipeline(
    char* sm, uint32_t smb, int tid, int wid, int lid, uint32_t tmem,
    const CUtensorMap* mAh, const CUtensorMap* mAl,
    const CUtensorMap* mBh, const CUtensorMap* mBl,
    int m0, int n0, int Ktot, uint32_t mbofs,
    int* gate, int gtar) {
    // Fallback (non-sm_103a PTX pass; never selected on GB300).
    (void)mAh; (void)mAl; (void)mBh; (void)mBl;
    if (gate && tid == 0) { while (atomicAdd(gate, 0) < gtar) {} __threadfence(); }
    __syncthreads();
    float* s_d = (float*)(sm + SM_TILES);
    const float* s_bias = (const float*)(sm + SM_BIAS);
    const __nv_bfloat16 *A_h, *A_l, *B_h, *B_l;
    if (Ktot == OBS) { A_h = g_sbar_h; A_l = g_sbar_l; B_h = g_W1T_h; B_l = g_W1T_l; }
    else if (mbofs == (uint32_t)(SM_MBAR + 1 * 48)) {
        A_h = g_h1_h; A_l = g_h1_l; B_h = g_W2T_h; B_l = g_W2T_l;
    } else {
        A_h = g_h2_h; A_l = g_h2_l; B_h = g_W3T_h; B_l = g_W3T_l;
    }
    for (int e = tid; e < 128 * 128; e += NTHR) {
        int r = e >> 7, c = e & 127;
        float acc = 0.f;
        for (int k = 0; k < Ktot; ++k) {
            float a = __bfloat162float(A_h[(size_t)(m0 + r) * Ktot + k]) +
                      __bfloat162float(A_l[(size_t)(m0 + r) * Ktot + k]);
            float b = __bfloat162float(B_h[(size_t)(n0 + c) * Ktot + k]) +
                      __bfloat162float(B_l[(size_t)(n0 + c) * Ktot + k]);
            acc += a * b;
        }
        s_d[r * STG_STRIDE + c] = acc + s_bias[c];
    }
    __syncthreads();
}
#endif

// ---------------------------------------------------------------------------
// Megakernel: phase1 -> phase2(+LN) -> phase3. grid (4, 32); 1 CTA/SM.
// ---------------------------------------------------------------------------
__global__ __launch_bounds__(NTHR, 1)
void mega_kernel(const int* __restrict__ action,
                 const float* __restrict__ W1,
                 const float* __restrict__ b1,
                 const float* __restrict__ b2,
                 const float* __restrict__ b3,
                 const float* __restrict__ ln_g,
                 const float* __restrict__ ln_b,
                 float* __restrict__ out) {
    extern __shared__ char sm[];
    const uint32_t smb = smem_u32(sm);
    const int tid = threadIdx.x;
    const int wid = tid >> 5;
    const int lid = tid & 31;
    const int x  = blockIdx.x;
    const int by = blockIdx.y;
    const int m0 = by * 128;

    float* s_bias = (float*)(sm + SM_BIAS);
    float* s_aux  = (float*)(sm + SM_AUX);
    int*   s_jrow = (int*)(sm + SM_JROW);
    float* s_b2   = (float*)(sm + SM_LNB2);
    float* s_mu   = (float*)(sm + SM_MU2);
    float* s_rs   = (float*)(sm + SM_RS2);
    float* s_d    = (float*)(sm + SM_TILES);

    uint32_t tmem = 0;
#if HAS_TCGEN05
    if (wid == 0) TCGEN05_ALLOC(smb + SM_TMEMPTR, 128);
    if (tid == 0) {
#pragma unroll
        for (int p = 0; p < 3; ++p) {
#pragma unroll
            for (int s = 0; s < NSLOT; ++s) {
                MBARRIER_INIT(smb + SM_MBAR + p * 48 + s * 8, 1);
                MBARRIER_INIT(smb + SM_MBAR + p * 48 + 24 + s * 8, 1);
            }
        }
    }
#endif
    // ---------------- phase 1: h1 ----------------
    {
        const int n0 = x * 128;
        if (tid < 128) {
            s_bias[tid] = b1[n0 + tid];
            s_jrow[tid] = (action[m0 + tid] & 3) * 128;
        }
        s_aux[tid] = W1[(size_t)(256 + (tid >> 7)) * HID + n0 + (tid & 127)];
        __syncthreads();
#if HAS_TCGEN05
        asm volatile("ld.shared.b32 %0, [%1];" : "=r"(tmem) : "r"(smb + SM_TMEMPTR));
#endif
        gemm_pipeline(sm, smb, tid, wid, lid, tmem,
                      &g_tmaps[0], &g_tmaps[1], &g_tmaps[2], &g_tmaps[3],
                      m0, n0, OBS, SM_MBAR + 0 * 48, nullptr, 0);
#pragma unroll
        for (int it = 0; it < 8; ++it) {
            int idx = it * NTHR + tid;
            int row = idx >> 5, c4 = (idx & 31) * 4;
            int jr = s_jrow[row];
            float4 v = *(float4*)&s_d[row * STG_STRIDE + c4];
            float f0 = fmaxf(v.x + 0.0625f * s_aux[jr + c4 + 0], 0.f);
            float f1 = fmaxf(v.y + 0.0625f * s_aux[jr + c4 + 1], 0.f);
            float f2 = fmaxf(v.z + 0.0625f * s_aux[jr + c4 + 2], 0.f);
            float f3 = fmaxf(v.w + 0.0625f * s_aux[jr + c4 + 3], 0.f);
            __nv_bfloat16 h0, l0, h1, l1, h2, l2, h3, l3;
            split_bf16(f0, h0, l0); split_bf16(f1, h1, l1);
            split_bf16(f2, h2, l2); split_bf16(f3, h3, l3);
            __nv_bfloat162 hp0(h0, h1), hp1(h2, h3), lp0(l0, l1), lp1(l2, l3);
            uint2 hv = make_uint2(*(uint32_t*)&hp0, *(uint32_t*)&hp1);
            uint2 lv = make_uint2(*(uint32_t*)&lp0, *(uint32_t*)&lp1);
            size_t o = (size_t)(m0 + row) * HID + n0 + c4;
            *(uint2*)(g_h1_h + o) = hv;
            *(uint2*)(g_h1_l + o) = lv;
        }
        band_arrive(&g_cnt1[by], tid);
    }

    // ---------------- phase 2: h2 = relu(LN(h1 @ W2 + b2)) ----------------
    {
        const int n0 = x * 128;
        if (tid < 128) {
            s_bias[tid] = b2[n0 + tid];
            s_aux[tid]  = ln_g[n0 + tid];
            s_b2[tid]   = ln_b[n0 + tid];
        }
        __syncthreads();
        gemm_pipeline(sm, smb, tid, wid, lid, tmem,
                      &g_tmaps[4], &g_tmaps[5], &g_tmaps[6], &g_tmaps[7],
                      m0, n0, HID, SM_MBAR + 1 * 48, &g_cnt1[by], 4);
        // per-row partials: 4 threads/row
        {
            int prow = tid >> 2, ph = tid & 3;
            float s = 0.f, ss = 0.f;
#pragma unroll
            for (int i = 0; i < 8; ++i) {
                float4 v = *(float4*)&s_d[prow * STG_STRIDE + ph * 32 + i * 4];
                s  += v.x + v.y + v.z + v.w;
                ss += v.x * v.x + v.y * v.y + v.z * v.z + v.w * v.w;
            }
            s  += __shfl_xor_sync(0xffffffffu, s, 1);
            ss += __shfl_xor_sync(0xffffffffu, ss, 1);
            s  += __shfl_xor_sync(0xffffffffu, s, 2);
            ss += __shfl_xor_sync(0xffffffffu, ss, 2);
            if (ph == 0) g_part[by][x][prow] = make_float2(s, ss);
        }
        band_arrive_wait(&g_cnt[by], 4, tid);
        if (tid < 128) {
            float ts = 0.f, tss = 0.f;
#pragma unroll
            for (int r = 0; r < 4; ++r) {
                float2 p = __ldcg(&g_part[by][r][tid]);
                ts += p.x; tss += p.y;
            }
            const float invn = 1.0f / HID;
            float mu = ts * invn;
            float var = tss * invn - mu * mu;
            s_mu[tid] = mu;
            s_rs[tid] = rsqrtf(var + 1e-5f);
        }
        __syncthreads();
#pragma unroll
        for (int it = 0; it < 8; ++it) {
            int idx = it * NTHR + tid;
            int row = idx >> 5, c4 = (idx & 31) * 4;
            float mu = s_mu[row], rs = s_rs[row];
            float4 v = *(float4*)&s_d[row * STG_STRIDE + c4];
            float f0 = fmaxf((v.x - mu) * rs * s_aux[c4 + 0] + s_b2[c4 + 0], 0.f);
            float f1 = fmaxf((v.y - mu) * rs * s_aux[c4 + 1] + s_b2[c4 + 1], 0.f);
            float f2 = fmaxf((v.z - mu) * rs * s_aux[c4 + 2] + s_b2[c4 + 2], 0.f);
            float f3 = fmaxf((v.w - mu) * rs * s_aux[c4 + 3] + s_b2[c4 + 3], 0.f);
            __nv_bfloat16 h0, l0, h1, l1, h2, l2, h3, l3;
            split_bf16(f0, h0, l0); split_bf16(f1, h1, l1);
            split_bf16(f2, h2, l2); split_bf16(f3, h3, l3);
            __nv_bfloat162 hp0(h0, h1), hp1(h2, h3), lp0(l0, l1), lp1(l2, l3);
            uint2 hv = make_uint2(*(uint32_t*)&hp0, *(uint32_t*)&hp1);
            uint2 lv = make_uint2(*(uint32_t*)&lp0, *(uint32_t*)&lp1);
            size_t o = (size_t)(m0 + row) * HID + n0 + c4;
            *(uint2*)(g_h2_h + o) = hv;
            *(uint2*)(g_h2_l + o) = lv;
        }
        band_arrive(&g_cnt2[by], tid);
    }

    // ---------------- phase 3: out = broadcast_obj(h2 @ W3 + b3) ----------
    {
        const int n0 = (x & 1) * 128;
        const int z  = x >> 1;
        if (tid < 128) s_bias[tid] = b3[n0 + tid];
        __syncthreads();
        gemm_pipeline(sm, smb, tid, wid, lid, tmem,
                      &g_tmaps[8], &g_tmaps[9], &g_tmaps[10], &g_tmaps[11],
                      m0, n0, HID, SM_MBAR + 2 * 48, &g_cnt2[by], 4);
#pragma unroll
        for (int it = 0; it < 8; ++it) {
            int idx = it * NTHR + tid;
            int row = idx >> 5, c4 = (idx & 31) * 4;
            float4 v = *(float4*)&s_d[row * STG_STRIDE + c4];
            size_t base = (size_t)(m0 + row) * (OBJ * OBS) +
                          (size_t)(z * 8) * OBS + n0 + c4;
#pragma unroll
            for (int ob = 0; ob < 8; ++ob)
                *(float4*)(out + base + (size_t)ob * OBS) = v;
        }
    }

#if HAS_TCGEN05
    __syncthreads();
    if (wid == 0) {
        TCGEN05_RELINQ();
        TCGEN05_DEALLOC(tmem, 128);
    }
#endif
}

// ---------------------------------------------------------------------------
// Host
// ---------------------------------------------------------------------------
typedef CUresult (*PFN_encodeTiled)(
    CUtensorMap*, CUtensorMapDataType, cuuint32_t, void*,
    const cuuint64_t*, const cuuint64_t*, const cuuint32_t*, const cuuint32_t*,
    CUtensorMapInterleave, CUtensorMapSwizzle, CUtensorMapL2promotion,
    CUtensorMapFloatOOBfill);

static void enc_map(PFN_encodeTiled f, CUtensorMap* m, void* base,
                    uint64_t K, uint64_t rows) {
    cuuint64_t dims[2] = {K, rows};
    cuuint64_t strides[1] = {K * 2};
    cuuint32_t box[2] = {64, 128};
    cuuint32_t es[2] = {1, 1};
    f(m, CU_TENSOR_MAP_DATA_TYPE_BFLOAT16, 2, base, dims, strides, box, es,
      CU_TENSOR_MAP_INTERLEAVE_NONE, CU_TENSOR_MAP_SWIZZLE_128B,
      CU_TENSOR_MAP_L2_PROMOTION_L2_128B, CU_TENSOR_MAP_FLOAT_OOB_FILL_NONE);
}

extern "C" void kernel_launch(void* const* d_in, const int* in_sizes, int n_in,
                              void* d_out, int out_size) {
    const float* states = (const float*)d_in[0];
    const int*   action = (const int*)d_in[1];
    const float* W1     = (const float*)d_in[2];
    const float* b1     = (const float*)d_in[3];
    const float* W2     = (const float*)d_in[4];
    const float* b2     = (const float*)d_in[5];
    const float* W3     = (const float*)d_in[6];
    const float* b3     = (const float*)d_in[7];
    const float* ln_g   = (const float*)d_in[8];
    const float* ln_b   = (const float*)d_in[9];
    float* out = (float*)d_out;

    void *sbh, *sbl, *h1h, *h1l, *h2h, *h2l;
    void *w1h, *w1l, *w2h, *w2l, *w3h, *w3l;
    cudaGetSymbolAddress(&sbh, g_sbar_h);
    cudaGetSymbolAddress(&sbl, g_sbar_l);
    cudaGetSymbolAddress(&h1h, g_h1_h);
    cudaGetSymbolAddress(&h1l, g_h1_l);
    cudaGetSymbolAddress(&h2h, g_h2_h);
    cudaGetSymbolAddress(&h2l, g_h2_l);
    cudaGetSymbolAddress(&w1h, g_W1T_h);
    cudaGetSymbolAddress(&w1l, g_W1T_l);
    cudaGetSymbolAddress(&w2h, g_W2T_h);
    cudaGetSymbolAddress(&w2l, g_W2T_l);
    cudaGetSymbolAddress(&w3h, g_W3T_h);
    cudaGetSymbolAddress(&w3l, g_W3T_l);

    static CUtensorMap h_maps[12];
    void* fp = nullptr;
    cudaDriverEntryPointQueryResult qres;
    cudaGetDriverEntryPoint("cuTensorMapEncodeTiled", &fp,
                            cudaEnableDefault, &qres);
    PFN_encodeTiled enc = (PFN_encodeTiled)fp;
    enc_map(enc, &h_maps[0],  sbh, OBS, BATCH);
    enc_map(enc, &h_maps[1],  sbl, OBS, BATCH);
    enc_map(enc, &h_maps[2],  w1h, OBS, HID);
    enc_map(enc, &h_maps[3],  w1l, OBS, HID);
    enc_map(enc, &h_maps[4],  h1h, HID, BATCH);
    enc_map(enc, &h_maps[5],  h1l, HID, BATCH);
    enc_map(enc, &h_maps[6],  w2h, HID, HID);
    enc_map(enc, &h_maps[7],  w2l, HID, HID);
    enc_map(enc, &h_maps[8],  h2h, HID, BATCH);
    enc_map(enc, &h_maps[9],  h2l, HID, BATCH);
    enc_map(enc, &h_maps[10], w3h, HID, OBS);
    enc_map(enc, &h_maps[11], w3l, HID, OBS);
    cudaMemcpyToSymbolAsync(g_tmaps, h_maps, sizeof(h_maps), 0,
                            cudaMemcpyHostToDevice, 0);

    cudaFuncSetAttribute(mega_kernel,
                         cudaFuncAttributeMaxDynamicSharedMemorySize, GEMM_SMEM);

    prep_kernel<<<1792, 256>>>(states, W1, W2, W3);
    mega_kernel<<<dim3(4, 32), NTHR, GEMM_SMEM>>>(
        action, W1, b1, b2, b3, ln_g, ln_b, out);
}